// round 1
// baseline (speedup 1.0000x reference)
#include <cuda_runtime.h>
#include <math.h>
#include <float.h>
#include <stdint.h>

#define B_    4
#define NIN_  4096
#define M_    16384
#define CIN_  256
#define COUT_ 128

// ---------------- scratch (no allocations allowed) ----------------
__device__ float g_bufA[B_ * COUT_ * NIN_];    // layer1 out (B,128,4096)
__device__ float g_bufB[B_ * COUT_ * NIN_];    // layer2 out (B,128,4096)
__device__ float g_featT[B_ * NIN_ * COUT_];   // layer3 out transposed (B,4096,128)
__device__ float g_wv[B_ * M_ * 3];            // interp weights
__device__ int   g_iv[B_ * M_ * 3];            // neighbor indices

// ---------------- fused Conv1d(k=1) + BN + ReLU GEMM ----------------
// Y(cout,n) = relu( (sum_k W[cout,k]*X[k,n] + b[cout] - rm[cout]) * g/sqrt(rv+eps) + beta )
// Tile: 128 cout x 64 n per block, K-step 32. 256 threads, 8x4 micro-tile.
__global__ __launch_bounds__(256) void mlp_kernel(
    const float* __restrict__ X, const float* __restrict__ W,
    const float* __restrict__ bias, const float* __restrict__ gamma,
    const float* __restrict__ betap, const float* __restrict__ rmean,
    const float* __restrict__ rvar, float* __restrict__ Y,
    int K, int transposed)
{
    __shared__ float Ws[32][COUT_];
    __shared__ float Xs[32][64];
    const int tid = threadIdx.x;
    const int b   = blockIdx.y;
    const int n0  = blockIdx.x * 64;
    const float* Xb = X + (size_t)b * K * NIN_;

    float acc[8][4];
#pragma unroll
    for (int i = 0; i < 8; i++)
#pragma unroll
        for (int j = 0; j < 4; j++) acc[i][j] = 0.f;

    const int rg    = tid >> 4;   // 0..15
    const int cg    = tid & 15;   // 0..15
    const int cout0 = rg * 8;
    const int nl    = cg * 4;

    for (int k0 = 0; k0 < K; k0 += 32) {
#pragma unroll
        for (int l = 0; l < 4; l++) {
            int idx = tid + l * 256;           // 0..1023
            int co  = idx & 127;
            int kq  = idx >> 7;                // 0..7
            float4 w4 = *(const float4*)(W + (size_t)co * K + k0 + kq * 4);
            Ws[kq * 4 + 0][co] = w4.x;
            Ws[kq * 4 + 1][co] = w4.y;
            Ws[kq * 4 + 2][co] = w4.z;
            Ws[kq * 4 + 3][co] = w4.w;
        }
#pragma unroll
        for (int l = 0; l < 2; l++) {
            int idx = tid + l * 256;           // 0..511
            int nq  = idx & 15;
            int kk  = idx >> 4;                // 0..31
            *(float4*)&Xs[kk][nq * 4] =
                *(const float4*)(Xb + (size_t)(k0 + kk) * NIN_ + n0 + nq * 4);
        }
        __syncthreads();
#pragma unroll
        for (int k = 0; k < 32; k++) {
            float4 xb = *(const float4*)&Xs[k][nl];
            float a0[8];
            *(float4*)&a0[0] = *(const float4*)&Ws[k][cout0];
            *(float4*)&a0[4] = *(const float4*)&Ws[k][cout0 + 4];
#pragma unroll
            for (int i = 0; i < 8; i++) {
                acc[i][0] = __fmaf_rn(a0[i], xb.x, acc[i][0]);
                acc[i][1] = __fmaf_rn(a0[i], xb.y, acc[i][1]);
                acc[i][2] = __fmaf_rn(a0[i], xb.z, acc[i][2]);
                acc[i][3] = __fmaf_rn(a0[i], xb.w, acc[i][3]);
            }
        }
        __syncthreads();
    }

    // epilogue: BN folded to scale/shift
    float sc[8], shf[8];
#pragma unroll
    for (int i = 0; i < 8; i++) {
        int c = cout0 + i;
        float s = gamma[c] / sqrtf(rvar[c] + 1e-5f);
        sc[i]  = s;
        shf[i] = betap[c] + (bias[c] - rmean[c]) * s;
    }

    if (!transposed) {
#pragma unroll
        for (int i = 0; i < 8; i++) {
            float4 v;
            v.x = fmaxf(__fmaf_rn(acc[i][0], sc[i], shf[i]), 0.f);
            v.y = fmaxf(__fmaf_rn(acc[i][1], sc[i], shf[i]), 0.f);
            v.z = fmaxf(__fmaf_rn(acc[i][2], sc[i], shf[i]), 0.f);
            v.w = fmaxf(__fmaf_rn(acc[i][3], sc[i], shf[i]), 0.f);
            *(float4*)(Y + ((size_t)b * COUT_ + cout0 + i) * NIN_ + n0 + nl) = v;
        }
    } else {
        // write featT[b][n][cout] (cout contiguous)
#pragma unroll
        for (int j = 0; j < 4; j++) {
            float v[8];
#pragma unroll
            for (int i = 0; i < 8; i++)
                v[i] = fmaxf(__fmaf_rn(acc[i][j], sc[i], shf[i]), 0.f);
            float* p = Y + ((size_t)b * NIN_ + n0 + nl + j) * COUT_ + cout0;
            *(float4*)(p)     = make_float4(v[0], v[1], v[2], v[3]);
            *(float4*)(p + 4) = make_float4(v[4], v[5], v[6], v[7]);
        }
    }
}

// ---------------- brute-force exact top-3 scan ----------------
// d2 replicates the reference algebra exactly:
//   sum_sq = (x*x + y*y) + z*z   (separately rounded, reduce-of-map)
//   dot    = fma(z,z', fma(y,y', x*x'))   (ascending-k FMA chain)
//   d2     = rn((sum_out + sum_in) - 2*dot)  via fma(-2, dot, t)
//   clamp < 0 -> 1e-7 BEFORE selection; strict-< insertion == stable top_k
__global__ __launch_bounds__(256) void scan_kernel(
    const float* __restrict__ xyzin, const float* __restrict__ xyzout,
    float* __restrict__ wout, int* __restrict__ iout)
{
    extern __shared__ float4 sh[];   // NIN_ entries: {x,y,z,sum_in}
    const int tid = threadIdx.x;
    const int b   = blockIdx.y;
    const float* pin = xyzin + (size_t)b * NIN_ * 3;

    for (int j = tid; j < NIN_; j += 256) {
        float x = pin[j * 3 + 0];
        float y = pin[j * 3 + 1];
        float z = pin[j * 3 + 2];
        float sn = __fadd_rn(__fadd_rn(__fmul_rn(x, x), __fmul_rn(y, y)),
                             __fmul_rn(z, z));
        sh[j] = make_float4(x, y, z, sn);
    }
    __syncthreads();

    const int m = blockIdx.x * 256 + tid;
    const float* q = xyzout + ((size_t)b * M_ + m) * 3;
    const float qx = q[0], qy = q[1], qz = q[2];
    const float qn = __fadd_rn(__fadd_rn(__fmul_rn(qx, qx), __fmul_rn(qy, qy)),
                               __fmul_rn(qz, qz));

    float s0 = FLT_MAX, s1 = FLT_MAX, s2 = FLT_MAX;
    int   i0 = 0, i1 = 0, i2 = 0;

#pragma unroll 4
    for (int j = 0; j < NIN_; j++) {
        float4 p = sh[j];
        float dot = __fmaf_rn(qz, p.z, __fmaf_rn(qy, p.y, __fmul_rn(qx, p.x)));
        float t   = __fadd_rn(qn, p.w);
        float d   = __fmaf_rn(-2.0f, dot, t);
        d = (d < 0.0f) ? 1e-7f : d;
        if (__builtin_expect(d < s2, 0)) {
            if (d < s1) {
                s2 = s1; i2 = i1;
                if (d < s0) { s1 = s0; i1 = i0; s0 = d; i0 = j; }
                else        { s1 = d;  i1 = j; }
            } else { s2 = d; i2 = j; }
        }
    }

    float w0 = __fdiv_rn(1.0f, s0);
    float w1 = __fdiv_rn(1.0f, s1);
    float w2 = __fdiv_rn(1.0f, s2);
    float ws = __fadd_rn(__fadd_rn(w0, w1), w2);
    size_t o = ((size_t)b * M_ + m) * 3;
    wout[o + 0] = __fdiv_rn(w0, ws);
    wout[o + 1] = __fdiv_rn(w1, ws);
    wout[o + 2] = __fdiv_rn(w2, ws);
    iout[o + 0] = i0;
    iout[o + 1] = i1;
    iout[o + 2] = i2;
}

// ---------------- gather + weighted interpolation ----------------
// out[b][c][m] = sum_k w_k * featT[b][idx_k][c]; smem-staged transposed write.
__global__ __launch_bounds__(128) void interp_kernel(
    const float* __restrict__ featT, const float* __restrict__ wv,
    const int* __restrict__ iv, float* __restrict__ out)
{
    __shared__ float sacc[64][COUT_ + 1];
    __shared__ float sw[64 * 3];
    __shared__ int   si[64 * 3];
    const int tid = threadIdx.x;
    const int b   = blockIdx.y;
    const int m0  = blockIdx.x * 64;
    const size_t base = ((size_t)b * M_ + m0) * 3;

    for (int l = tid; l < 192; l += 128) {
        sw[l] = wv[base + l];
        si[l] = iv[base + l];
    }
    __syncthreads();

    const float* fb = featT + (size_t)b * NIN_ * COUT_;
    const int c = tid;
#pragma unroll 2
    for (int qq = 0; qq < 64; qq++) {
        float w0 = sw[qq * 3], w1 = sw[qq * 3 + 1], w2 = sw[qq * 3 + 2];
        const float* f0 = fb + (size_t)si[qq * 3]     * COUT_;
        const float* f1 = fb + (size_t)si[qq * 3 + 1] * COUT_;
        const float* f2 = fb + (size_t)si[qq * 3 + 2] * COUT_;
        sacc[qq][c] = __fmaf_rn(w2, f2[c],
                      __fmaf_rn(w1, f1[c], __fmul_rn(w0, f0[c])));
    }
    __syncthreads();

#pragma unroll
    for (int cc = 0; cc < COUT_; cc += 2) {
        int ci = cc + (tid >> 6);
        int mi = tid & 63;
        out[((size_t)b * COUT_ + ci) * M_ + m0 + mi] = sacc[mi][ci];
    }
}

// ---------------- launch ----------------
extern "C" void kernel_launch(void* const* d_in, const int* in_sizes, int n_in,
                              void* d_out, int out_size)
{
    (void)in_sizes; (void)n_in; (void)out_size;
    const float* rgb    = (const float*)d_in[0];
    const float* xyzin  = (const float*)d_in[1];
    const float* xyzout = (const float*)d_in[2];
    const float* w1 = (const float*)d_in[3];
    const float* b1 = (const float*)d_in[4];
    const float* g1 = (const float*)d_in[5];
    const float* be1 = (const float*)d_in[6];
    const float* rm1 = (const float*)d_in[7];
    const float* rv1 = (const float*)d_in[8];
    const float* w2 = (const float*)d_in[9];
    const float* b2 = (const float*)d_in[10];
    const float* g2 = (const float*)d_in[11];
    const float* be2 = (const float*)d_in[12];
    const float* rm2 = (const float*)d_in[13];
    const float* rv2 = (const float*)d_in[14];
    const float* w3 = (const float*)d_in[15];
    const float* b3 = (const float*)d_in[16];
    const float* g3 = (const float*)d_in[17];
    const float* be3 = (const float*)d_in[18];
    const float* rm3 = (const float*)d_in[19];
    const float* rv3 = (const float*)d_in[20];
    float* out = (float*)d_out;

    float *bufA, *bufB, *featT, *wvp;
    int* ivp;
    cudaGetSymbolAddress((void**)&bufA,  g_bufA);
    cudaGetSymbolAddress((void**)&bufB,  g_bufB);
    cudaGetSymbolAddress((void**)&featT, g_featT);
    cudaGetSymbolAddress((void**)&wvp,   g_wv);
    cudaGetSymbolAddress((void**)&ivp,   g_iv);

    dim3 gemm_grid(NIN_ / 64, B_);
    mlp_kernel<<<gemm_grid, 256>>>(rgb,  w1, b1, g1, be1, rm1, rv1, bufA,  CIN_,  0);
    mlp_kernel<<<gemm_grid, 256>>>(bufA, w2, b2, g2, be2, rm2, rv2, bufB,  COUT_, 0);
    mlp_kernel<<<gemm_grid, 256>>>(bufB, w3, b3, g3, be3, rm3, rv3, featT, COUT_, 1);

    cudaFuncSetAttribute(scan_kernel,
                         cudaFuncAttributeMaxDynamicSharedMemorySize,
                         NIN_ * sizeof(float4));
    dim3 scan_grid(M_ / 256, B_);
    scan_kernel<<<scan_grid, 256, NIN_ * sizeof(float4)>>>(xyzin, xyzout, wvp, ivp);

    dim3 interp_grid(M_ / 64, B_);
    interp_kernel<<<interp_grid, 128>>>(featT, wvp, ivp, out);
}